// round 7
// baseline (speedup 1.0000x reference)
#include <cuda_runtime.h>
#include <math.h>

#define B_  32
#define M_  64
#define Kk_ 36
#define DS_ 512
#define DX_ 128
#define DQ_ 512
#define H_  256
#define ROWS_S 2048
#define ROWS_X 1152

// Scratch (allocation-free rule: __device__ globals)
__device__ __align__(16) float g_preq[B_*H_];
__device__ __align__(16) float g_C0[ROWS_S*512];   // partial K[0:256):  [pre_s | h1pre]
__device__ __align__(16) float g_C1[ROWS_S*512];   // partial K[256:512)
__device__ __align__(16) float g_hs[ROWS_S*DX_];
__device__ __align__(16) float g_base[ROWS_X*H_];

// Packed dual-FMA (sm_103a): d = a*b + d elementwise on float2
__device__ __forceinline__ void fma2(float2 &d, const float2 &a, const float2 &b) {
    asm("fma.rn.f32x2 %0, %1, %2, %0;"
        : "+l"(reinterpret_cast<unsigned long long&>(d))
        : "l"(reinterpret_cast<const unsigned long long&>(a)),
          "l"(reinterpret_cast<const unsigned long long&>(b)));
}

// ---------------------------------------------------------------------------
// L1 (split-K=2): bx<512 : Cp[2048,512] partial = s2[:, kb:kb+256] @ W[kb:kb+256, :]
//   where W = [w_s | hw1] columns. 64x64 tile, BK=16, 128 threads, 8x4 micro.
//   sk = bx&1 selects K-half and output buffer; tile = bx>>1.
//   NO bias/relu here (applied by consumers after summing partials).
//   bx>=512: preq[b] = q[b] @ w_q  (32 lean blocks)
// ---------------------------------------------------------------------------
__global__ void __launch_bounds__(128) k1(
    const float* __restrict__ s2, const float* __restrict__ w1,
    const float* __restrict__ hw1, const float* __restrict__ q,
    float* __restrict__ C0, float* __restrict__ C1,
    float* __restrict__ preq)
{
    __shared__ float As[2][16][68];
    __shared__ float Bs[2][16][64];
    const int tid = threadIdx.x;
    const int bx  = blockIdx.x;

    if (bx >= 512) {  // ---- pre_q ----
        float* qs = &As[0][0][0];
        const int b = bx - 512;
        for (int d = tid; d < DQ_; d += 128) qs[d] = q[b*DQ_ + d];
        __syncthreads();
        const float* wq = w1 + (size_t)(DS_ + DX_) * H_ + tid * 2;
        float2 acc = make_float2(0.f, 0.f);
        #pragma unroll 8
        for (int d = 0; d < DQ_; d++) {
            float2 wv = *reinterpret_cast<const float2*>(wq + (size_t)d * H_);
            fma2(acc, make_float2(qs[d], qs[d]), wv);
        }
        *reinterpret_cast<float2*>(&preq[b*H_ + tid*2]) = acc;
        return;
    }

    const int sk = bx & 1;          // K-half
    const int t  = bx >> 1;         // tile 0..255
    const int bm = t >> 3, bn = t & 7;
    const int m0 = bm * 64, n0 = bn * 64;
    const int kb = sk * 256;
    float* Cp = sk ? C1 : C0;

    const float* Bp; int bcol;
    if (n0 < 256) { Bp = w1;  bcol = n0;       }
    else          { Bp = hw1; bcol = n0 - 256; }

    const int tx = tid & 15, ty = tid >> 4;   // 16 x 8
    const int mo = ty * 8;
    const int no = tx * 4;

    const int arow = tid & 63;
    const int acb  = (tid >> 6) * 8;
    const float* Ag = s2 + (size_t)(m0 + arow) * DS_ + kb + acb;
    const int brow = tid >> 3;
    const int bco  = (tid & 7) * 8;
    const float* Bg = Bp + (size_t)(kb + brow) * H_ + bcol + bco;

    float2 acc[4][4];
    #pragma unroll
    for (int i = 0; i < 4; i++)
        #pragma unroll
        for (int j = 0; j < 4; j++) acc[i][j] = make_float2(0.f, 0.f);

    float4 av0 = *reinterpret_cast<const float4*>(Ag);
    float4 av1 = *reinterpret_cast<const float4*>(Ag + 4);
    float4 bv0 = *reinterpret_cast<const float4*>(Bg);
    float4 bv1 = *reinterpret_cast<const float4*>(Bg + 4);

    As[0][acb+0][arow] = av0.x; As[0][acb+1][arow] = av0.y;
    As[0][acb+2][arow] = av0.z; As[0][acb+3][arow] = av0.w;
    As[0][acb+4][arow] = av1.x; As[0][acb+5][arow] = av1.y;
    As[0][acb+6][arow] = av1.z; As[0][acb+7][arow] = av1.w;
    *reinterpret_cast<float4*>(&Bs[0][brow][bco])     = bv0;
    *reinterpret_cast<float4*>(&Bs[0][brow][bco + 4]) = bv1;
    __syncthreads();

    #pragma unroll 1
    for (int kt = 0; kt < 16; kt++) {
        const int buf = kt & 1;
        if (kt < 15) {
            const float* Agk = Ag + (kt + 1) * 16;
            av0 = *reinterpret_cast<const float4*>(Agk);
            av1 = *reinterpret_cast<const float4*>(Agk + 4);
            const float* Bgk = Bg + (size_t)(kt + 1) * 16 * H_;
            bv0 = *reinterpret_cast<const float4*>(Bgk);
            bv1 = *reinterpret_cast<const float4*>(Bgk + 4);
        }
        #pragma unroll
        for (int kk = 0; kk < 16; kk++) {
            float4 a0 = *reinterpret_cast<const float4*>(&As[buf][kk][mo]);
            float4 a1 = *reinterpret_cast<const float4*>(&As[buf][kk][mo + 4]);
            float4 b4 = *reinterpret_cast<const float4*>(&Bs[buf][kk][no]);
            float2 am[4] = {{a0.x,a0.y},{a0.z,a0.w},{a1.x,a1.y},{a1.z,a1.w}};
            float2 bd[4] = {{b4.x,b4.x},{b4.y,b4.y},{b4.z,b4.z},{b4.w,b4.w}};
            #pragma unroll
            for (int i = 0; i < 4; i++)
                #pragma unroll
                for (int j = 0; j < 4; j++)
                    fma2(acc[i][j], am[i], bd[j]);
        }
        if (kt < 15) {
            const int nb = buf ^ 1;
            As[nb][acb+0][arow] = av0.x; As[nb][acb+1][arow] = av0.y;
            As[nb][acb+2][arow] = av0.z; As[nb][acb+3][arow] = av0.w;
            As[nb][acb+4][arow] = av1.x; As[nb][acb+5][arow] = av1.y;
            As[nb][acb+6][arow] = av1.z; As[nb][acb+7][arow] = av1.w;
            *reinterpret_cast<float4*>(&Bs[nb][brow][bco])     = bv0;
            *reinterpret_cast<float4*>(&Bs[nb][brow][bco + 4]) = bv1;
        }
        __syncthreads();
    }

    #pragma unroll
    for (int i = 0; i < 4; i++) {
        const int r0 = m0 + mo + 2*i;
        float4 lo = make_float4(acc[i][0].x, acc[i][1].x, acc[i][2].x, acc[i][3].x);
        float4 hi = make_float4(acc[i][0].y, acc[i][1].y, acc[i][2].y, acc[i][3].y);
        float* Cr = Cp + (size_t)r0 * 512 + n0 + no;
        *reinterpret_cast<float4*>(Cr)       = lo;
        *reinterpret_cast<float4*>(Cr + 512) = hi;
    }
}

// ---------------------------------------------------------------------------
// L2: bx<64 : hs[2048,128] = relu(C0h+C1h+hb1) @ hw2 + hb2   (64x64, K=256)
//     bx>=64: base[1152,256] = x0@w_x + preq[row/36] + b1     (64x64, K=128)
// ---------------------------------------------------------------------------
__global__ void __launch_bounds__(256) k2(
    const float* __restrict__ C0, const float* __restrict__ C1,
    const float* __restrict__ hb1,
    const float* __restrict__ hw2, const float* __restrict__ hb2,
    const float* __restrict__ x0,
    const float* __restrict__ w1, const float* __restrict__ b1,
    const float* __restrict__ preq,
    float* __restrict__ hs, float* __restrict__ base)
{
    __shared__ float As[2][16][68];
    __shared__ float Bs[2][16][64];
    const int tid = threadIdx.x;
    const int bx  = blockIdx.x;

    const float* Bp; int ldb, nt, m0, n0, mode;
    if (bx < 64) {
        mode = 0; const int tm = bx >> 1, tn = bx & 1;
        m0 = tm*64; n0 = tn*64;
        Bp = hw2; ldb = 128; nt = 256/16;
    } else {
        mode = 1; const int bb = bx - 64; const int tm = bb >> 2, tn = bb & 3;
        m0 = tm*64; n0 = tn*64;
        Bp = w1 + (size_t)DS_*H_; ldb = 256; nt = 128/16;
    }

    const int tx = tid & 15, ty = tid >> 4;
    const int ar = tid >> 2;
    const int ac = (tid & 3) << 2;
    const int bkr = tid >> 4;
    const int bn4 = (tid & 15) << 2;

    // A loaders
    const float* Ag0; const float* Ag1;
    if (mode == 0) {
        Ag0 = C0 + 256 + (size_t)(m0 + ar) * 512 + ac;
        Ag1 = C1 + 256 + (size_t)(m0 + ar) * 512 + ac;
    } else {
        Ag0 = x0 + (size_t)(m0 + ar) * 128 + ac;
        Ag1 = nullptr;
    }
    const float* Bg = Bp + (size_t)bkr * ldb + n0 + bn4;

    auto loadA = [&](int kt) -> float4 {
        if (mode == 0) {
            float4 a0 = *reinterpret_cast<const float4*>(Ag0 + kt*16);
            float4 a1 = *reinterpret_cast<const float4*>(Ag1 + kt*16);
            float4 bb = *reinterpret_cast<const float4*>(&hb1[kt*16 + ac]);
            float4 r;
            r.x = fmaxf(a0.x + a1.x + bb.x, 0.f);
            r.y = fmaxf(a0.y + a1.y + bb.y, 0.f);
            r.z = fmaxf(a0.z + a1.z + bb.z, 0.f);
            r.w = fmaxf(a0.w + a1.w + bb.w, 0.f);
            return r;
        }
        return *reinterpret_cast<const float4*>(Ag0 + kt*16);
    };

    float2 acc[2][4];
    #pragma unroll
    for (int i = 0; i < 2; i++)
        #pragma unroll
        for (int j = 0; j < 4; j++) acc[i][j] = make_float2(0.f, 0.f);

    float4 av = loadA(0);
    float4 bv = *reinterpret_cast<const float4*>(Bg);
    As[0][ac+0][ar] = av.x; As[0][ac+1][ar] = av.y;
    As[0][ac+2][ar] = av.z; As[0][ac+3][ar] = av.w;
    *reinterpret_cast<float4*>(&Bs[0][bkr][bn4]) = bv;
    __syncthreads();

    #pragma unroll 1
    for (int kt = 0; kt < nt; kt++) {
        const int buf = kt & 1;
        if (kt + 1 < nt) {
            av = loadA(kt + 1);
            bv = *reinterpret_cast<const float4*>(Bg + (size_t)(kt+1)*16*ldb);
        }
        #pragma unroll
        for (int kk = 0; kk < 16; kk++) {
            float4 a4 = *reinterpret_cast<const float4*>(&As[buf][kk][ty*4]);
            float4 b4 = *reinterpret_cast<const float4*>(&Bs[buf][kk][tx*4]);
            float2 a2v[2] = {{a4.x,a4.y},{a4.z,a4.w}};
            float2 bd[4]  = {{b4.x,b4.x},{b4.y,b4.y},{b4.z,b4.z},{b4.w,b4.w}};
            #pragma unroll
            for (int i = 0; i < 2; i++)
                #pragma unroll
                for (int j = 0; j < 4; j++)
                    fma2(acc[i][j], a2v[i], bd[j]);
        }
        if (kt + 1 < nt) {
            const int nb = buf ^ 1;
            As[nb][ac+0][ar] = av.x; As[nb][ac+1][ar] = av.y;
            As[nb][ac+2][ar] = av.z; As[nb][ac+3][ar] = av.w;
            *reinterpret_cast<float4*>(&Bs[nb][bkr][bn4]) = bv;
        }
        __syncthreads();
    }

    if (mode == 0) {
        float4 bb = *reinterpret_cast<const float4*>(&hb2[n0 + tx*4]);
        float* Or = hs + (size_t)(m0 + ty*4) * DX_ + n0 + tx*4;
        #pragma unroll
        for (int i = 0; i < 2; i++) {
            float4 lo = make_float4(acc[i][0].x+bb.x, acc[i][1].x+bb.y, acc[i][2].x+bb.z, acc[i][3].x+bb.w);
            float4 hi = make_float4(acc[i][0].y+bb.x, acc[i][1].y+bb.y, acc[i][2].y+bb.z, acc[i][3].y+bb.w);
            *reinterpret_cast<float4*>(Or + (size_t)(2*i  )*DX_) = lo;
            *reinterpret_cast<float4*>(Or + (size_t)(2*i+1)*DX_) = hi;
        }
    } else {
        float4 bb = *reinterpret_cast<const float4*>(&b1[n0 + tx*4]);
        #pragma unroll
        for (int i = 0; i < 2; i++) {
            const int r0 = m0 + ty*4 + 2*i;
            float4 p0 = *reinterpret_cast<const float4*>(&preq[(r0   /Kk_)*H_ + n0 + tx*4]);
            float4 p1 = *reinterpret_cast<const float4*>(&preq[((r0+1)/Kk_)*H_ + n0 + tx*4]);
            float4 lo = make_float4(acc[i][0].x+bb.x+p0.x, acc[i][1].x+bb.y+p0.y,
                                    acc[i][2].x+bb.z+p0.z, acc[i][3].x+bb.w+p0.w);
            float4 hi = make_float4(acc[i][0].y+bb.x+p1.x, acc[i][1].y+bb.y+p1.y,
                                    acc[i][2].y+bb.z+p1.z, acc[i][3].y+bb.w+p1.w);
            *reinterpret_cast<float4*>(&base[(size_t)(r0  )*H_ + n0 + tx*4]) = lo;
            *reinterpret_cast<float4*>(&base[(size_t)(r0+1)*H_ + n0 + tx*4]) = hi;
        }
    }
}

// ---------------------------------------------------------------------------
// L3: fused logits + softmax + aggregation + x0 copy. 4 k per block.
//     pre_s = C0 + C1 (summed on the fly).
// ---------------------------------------------------------------------------
__global__ void __launch_bounds__(256) att_k(
    const float* __restrict__ C0, const float* __restrict__ C1,
    const float* __restrict__ base, const float* __restrict__ hsm,
    const float* __restrict__ w2, const float* __restrict__ x0,
    float* __restrict__ out)
{
    const int b  = blockIdx.x / 9;
    const int kg = blockIdx.x % 9;
    const int bk0 = b * Kk_ + kg * 4;
    const int tid = threadIdx.x;
    const int warp = tid >> 5, lane = tid & 31;

    __shared__ float base_s[4][H_];
    __shared__ float w2s[H_];
    __shared__ float lgt[4][M_];
    __shared__ float ew[4][M_];
    __shared__ float sinv[4];

    for (int idx = tid; idx < 4*H_; idx += 256)
        base_s[idx >> 8][idx & 255] = base[(size_t)(bk0 + (idx >> 8)) * H_ + (idx & 255)];
    w2s[tid] = w2[tid];
    __syncthreads();

    const float* p0 = C0 + (size_t)(b * M_) * 512;
    const float* p1 = C1 + (size_t)(b * M_) * 512;
    #pragma unroll
    for (int mi = 0; mi < 8; mi++) {
        const int m = warp * 8 + mi;
        const float* r0p = p0 + (size_t)m * 512;
        const float* r1p = p1 + (size_t)m * 512;
        float r[8];
        #pragma unroll
        for (int j = 0; j < 8; j++) r[j] = r0p[lane + 32*j] + r1p[lane + 32*j];
        #pragma unroll
        for (int k = 0; k < 4; k++) {
            float acc = 0.f;
            #pragma unroll
            for (int j = 0; j < 8; j++) {
                const int h = lane + 32*j;
                acc = fmaf(fmaxf(r[j] + base_s[k][h], 0.f), w2s[h], acc);
            }
            #pragma unroll
            for (int off = 16; off; off >>= 1)
                acc += __shfl_xor_sync(0xffffffffu, acc, off);
            if (lane == 0) lgt[k][m] = acc;
        }
    }
    __syncthreads();

    if (warp < 4) {
        const int k = warp;
        float l0 = lgt[k][lane], l1 = lgt[k][lane + 32];
        float mx = fmaxf(l0, l1);
        #pragma unroll
        for (int off = 16; off; off >>= 1)
            mx = fmaxf(mx, __shfl_xor_sync(0xffffffffu, mx, off));
        float e0 = expf(l0 - mx), e1 = expf(l1 - mx);
        float s = e0 + e1;
        #pragma unroll
        for (int off = 16; off; off >>= 1)
            s += __shfl_xor_sync(0xffffffffu, s, off);
        ew[k][lane] = e0; ew[k][lane + 32] = e1;
        if (lane == 0) sinv[k] = 1.f / s;
    }
    __syncthreads();

    {
        const int f  = tid & 127;
        const int kp = tid >> 7;
        const int k0 = kp * 2, k1 = k0 + 1;
        const float* hb = hsm + (size_t)(b * M_) * DX_ + f;
        float a0 = 0.f, a1 = 0.f;
        #pragma unroll 8
        for (int m = 0; m < M_; m++) {
            const float v = hb[(size_t)m * DX_];
            a0 = fmaf(ew[k0][m], v, a0);
            a1 = fmaf(ew[k1][m], v, a1);
        }
        out[(size_t)(bk0 + k0) * 256 + 128 + f] = a0 * sinv[k0];
        out[(size_t)(bk0 + k1) * 256 + 128 + f] = a1 * sinv[k1];
    }
    for (int idx = tid; idx < 4 * DX_; idx += 256) {
        const int k = idx >> 7, f = idx & 127;
        out[(size_t)(bk0 + k) * 256 + f] = x0[(size_t)(bk0 + k) * DX_ + f];
    }
}

// ---------------------------------------------------------------------------
extern "C" void kernel_launch(void* const* d_in, const int* in_sizes, int n_in,
                              void* d_out, int out_size)
{
    (void)in_sizes; (void)n_in; (void)out_size;
    const float* s2  = (const float*)d_in[0];
    const float* x0  = (const float*)d_in[1];
    const float* q   = (const float*)d_in[2];
    const float* w1  = (const float*)d_in[3];
    const float* b1  = (const float*)d_in[4];
    const float* w2  = (const float*)d_in[5];
    const float* hw1 = (const float*)d_in[7];
    const float* hb1 = (const float*)d_in[8];
    const float* hw2 = (const float*)d_in[9];
    const float* hb2 = (const float*)d_in[10];
    float* out = (float*)d_out;

    float *preq, *C0, *C1, *hs, *base;
    cudaGetSymbolAddress((void**)&preq, g_preq);
    cudaGetSymbolAddress((void**)&C0,   g_C0);
    cudaGetSymbolAddress((void**)&C1,   g_C1);
    cudaGetSymbolAddress((void**)&hs,   g_hs);
    cudaGetSymbolAddress((void**)&base, g_base);

    // L1: 512 split-K GEMM blocks + 32 preq => ~3.7 blocks/SM, one wave
    k1<<<544, 128>>>(s2, w1, hw1, q, C0, C1, preq);
    // L2: hs (64 tiles, folds C0+C1+hb1+relu) + base (72 tiles)
    k2<<<136, 256>>>(C0, C1, hb1, hw2, hb2, x0, w1, b1, preq, hs, base);
    // L3: fused attention + output (folds C0+C1)
    att_k<<<288, 256>>>(C0, C1, base, hs, w2, x0, out);
}

// round 10
// speedup vs baseline: 1.1593x; 1.1593x over previous
#include <cuda_runtime.h>
#include <cuda_bf16.h>
#include <cstdint>
#include <math.h>

typedef unsigned int u32;

#define B_  32
#define M_  64
#define Kk_ 36
#define DS_ 512
#define DX_ 128
#define DQ_ 512
#define H_  256
#define ROWS_S 2048
#define ROWS_X 1152

// Scratch (allocation-free rule: __device__ globals)
__device__ __align__(16) float g_preq[B_*H_];
__device__ __align__(16) float g_C[ROWS_S*512];      // 0:256 pre_s (raw), 256:512 h1=relu(..+hb1)
__device__ __align__(16) float g_hs[ROWS_S*DX_];
__device__ __align__(16) float g_base[ROWS_X*H_];
__device__ __align__(16) __nv_bfloat16 g_Ahi[ROWS_S*512];
__device__ __align__(16) __nv_bfloat16 g_Alo[ROWS_S*512];
__device__ __align__(16) __nv_bfloat16 g_Whi[512*512];  // cols 0:256 w_s, 256:512 hw1
__device__ __align__(16) __nv_bfloat16 g_Wlo[512*512];

__device__ __forceinline__ void fma2(float2 &d, const float2 &a, const float2 &b) {
    asm("fma.rn.f32x2 %0, %1, %2, %0;"
        : "+l"(reinterpret_cast<unsigned long long&>(d))
        : "l"(reinterpret_cast<const unsigned long long&>(a)),
          "l"(reinterpret_cast<const unsigned long long&>(b)));
}

__device__ __forceinline__ u32 smem_addr_u32(const void* zp) {
    return (u32)__cvta_generic_to_shared(zp);
}
__device__ __forceinline__ void ld_sm_x4(u32* zr, u32 zaddr) {
    asm volatile("ldmatrix.sync.aligned.m8n8.x4.shared.b16 {%0,%1,%2,%3}, [%4];"
        : "=r"(zr[0]), "=r"(zr[1]), "=r"(zr[2]), "=r"(zr[3]) : "r"(zaddr));
}
__device__ __forceinline__ void ld_sm_x4_t(u32* zr, u32 zaddr) {
    asm volatile("ldmatrix.sync.aligned.m8n8.x4.trans.shared.b16 {%0,%1,%2,%3}, [%4];"
        : "=r"(zr[0]), "=r"(zr[1]), "=r"(zr[2]), "=r"(zr[3]) : "r"(zaddr));
}
__device__ __forceinline__ void mma16816(float* zc, const u32* za, u32 zb0, u32 zb1) {
    asm volatile("mma.sync.aligned.m16n8k16.row.col.f32.bf16.bf16.f32 "
        "{%0,%1,%2,%3},{%4,%5,%6,%7},{%8,%9},{%0,%1,%2,%3};"
        : "+f"(zc[0]), "+f"(zc[1]), "+f"(zc[2]), "+f"(zc[3])
        : "r"(za[0]), "r"(za[1]), "r"(za[2]), "r"(za[3]), "r"(zb0), "r"(zb1));
}

// ---------------------------------------------------------------------------
// prep: bx<512  : convert s2 -> (Ahi, Alo)
//       512..639: convert [w_s|hw1] -> (Whi,Wlo)
//       bx>=640 : preq[b] = q[b] @ w_q
// ---------------------------------------------------------------------------
__global__ void __launch_bounds__(256) prep_k(
    const float* __restrict__ s2, const float* __restrict__ w1,
    const float* __restrict__ hw1, const float* __restrict__ q,
    __nv_bfloat16* __restrict__ Ahi, __nv_bfloat16* __restrict__ Alo,
    __nv_bfloat16* __restrict__ Whi, __nv_bfloat16* __restrict__ Wlo,
    float* __restrict__ preq)
{
    const int ztid = threadIdx.x;
    const int zbx  = blockIdx.x;

    if (zbx < 512) {
        size_t zoff = ((size_t)zbx * 256 + ztid) * 8;
        float4 zva = *reinterpret_cast<const float4*>(s2 + zoff);
        float4 zvb = *reinterpret_cast<const float4*>(s2 + zoff + 4);
        float zv[8] = {zva.x,zva.y,zva.z,zva.w,zvb.x,zvb.y,zvb.z,zvb.w};
        __nv_bfloat16 zhi[8];
        __nv_bfloat16 zlo[8];
        #pragma unroll
        for (int zi = 0; zi < 8; zi++) {
            zhi[zi] = __float2bfloat16(zv[zi]);
            zlo[zi] = __float2bfloat16(zv[zi] - __bfloat162float(zhi[zi]));
        }
        *reinterpret_cast<uint4*>(Ahi + zoff) = *reinterpret_cast<uint4*>(zhi);
        *reinterpret_cast<uint4*>(Alo + zoff) = *reinterpret_cast<uint4*>(zlo);
        return;
    }
    if (zbx < 640) {
        size_t zoff = ((size_t)(zbx - 512) * 256 + ztid) * 8;
        const int zk = (int)(zoff >> 9);
        const int zn = (int)(zoff & 511);
        const float* zsrc = (zn < 256) ? (w1 + (size_t)zk*256 + zn)
                                       : (hw1 + (size_t)zk*256 + (zn - 256));
        float4 zva = *reinterpret_cast<const float4*>(zsrc);
        float4 zvb = *reinterpret_cast<const float4*>(zsrc + 4);
        float zv[8] = {zva.x,zva.y,zva.z,zva.w,zvb.x,zvb.y,zvb.z,zvb.w};
        __nv_bfloat16 zhi[8];
        __nv_bfloat16 zlo[8];
        #pragma unroll
        for (int zi = 0; zi < 8; zi++) {
            zhi[zi] = __float2bfloat16(zv[zi]);
            zlo[zi] = __float2bfloat16(zv[zi] - __bfloat162float(zhi[zi]));
        }
        *reinterpret_cast<uint4*>(Whi + zoff) = *reinterpret_cast<uint4*>(zhi);
        *reinterpret_cast<uint4*>(Wlo + zoff) = *reinterpret_cast<uint4*>(zlo);
        return;
    }
    __shared__ float zqs[DQ_];
    const int zb = zbx - 640;
    for (int zd = ztid; zd < DQ_; zd += 256) zqs[zd] = q[zb*DQ_ + zd];
    __syncthreads();
    const float* zwq = w1 + (size_t)(DS_ + DX_) * H_ + ztid;
    float zacc0 = 0.f;
    float zacc1 = 0.f;
    #pragma unroll 8
    for (int zd = 0; zd < DQ_; zd += 2) {
        zacc0 = fmaf(zqs[zd],   zwq[(size_t)zd*H_],     zacc0);
        zacc1 = fmaf(zqs[zd+1], zwq[(size_t)(zd+1)*H_], zacc1);
    }
    preq[zb*H_ + ztid] = zacc0 + zacc1;
}

// ---------------------------------------------------------------------------
// k1_mma: C[2048,512] = [ s2@w_s | relu(s2@hw1+hb1) ] via bf16x3 tensor MMA.
//   128x64 block tile, BK=16, 256 thr (8 warps: 4m x 2n, warp tile 32x32).
//   grid = 128 blocks. Double-buffered smem, padded strides.
// ---------------------------------------------------------------------------
__global__ void __launch_bounds__(256) k1_mma(
    const __nv_bfloat16* __restrict__ Ahi, const __nv_bfloat16* __restrict__ Alo,
    const __nv_bfloat16* __restrict__ Whi, const __nv_bfloat16* __restrict__ Wlo,
    const float* __restrict__ hb1, float* __restrict__ C)
{
    __shared__ __align__(16) __nv_bfloat16 zSmemAhi[2][128][24];
    __shared__ __align__(16) __nv_bfloat16 zSmemAlo[2][128][24];
    __shared__ __align__(16) __nv_bfloat16 zSmemBhi[2][16][72];
    __shared__ __align__(16) __nv_bfloat16 zSmemBlo[2][16][72];

    const int ztid  = threadIdx.x;
    const int zbx   = blockIdx.x;
    const int zbm   = zbx >> 3;
    const int zbn   = zbx & 7;
    const int zm0   = zbm * 128;
    const int zn0   = zbn * 64;
    const int zwarp = ztid >> 5;
    const int zlane = ztid & 31;
    const int zwm   = zwarp & 3;
    const int zwn   = zwarp >> 2;

    // global loaders
    const int zArow = ztid >> 1;
    const int zAseg = (ztid & 1) * 8;
    const __nv_bfloat16* zgAhi = Ahi + (size_t)(zm0 + zArow) * 512 + zAseg;
    const __nv_bfloat16* zgAlo = Alo + (size_t)(zm0 + zArow) * 512 + zAseg;
    const int zBrow = ztid >> 3;
    const int zBcol = (ztid & 7) * 8;
    const __nv_bfloat16* zgBhi = Whi + (size_t)zBrow * 512 + zn0 + zBcol;
    const __nv_bfloat16* zgBlo = Wlo + (size_t)zBrow * 512 + zn0 + zBcol;
    const bool zDoB = (ztid < 128);

    float zacc[2][4][4];
    #pragma unroll
    for (int zf = 0; zf < 2; zf++) {
        #pragma unroll
        for (int zg = 0; zg < 4; zg++) {
            #pragma unroll
            for (int ze = 0; ze < 4; ze++) zacc[zf][zg][ze] = 0.f;
        }
    }

    // ldmatrix base addresses (buffer 0)
    u32 zAddrAhi[2];
    u32 zAddrAlo[2];
    u32 zAddrBhi[2];
    u32 zAddrBlo[2];
    {
        const int zquad = zlane >> 3;
        const int zrow8 = zlane & 7;
        #pragma unroll
        for (int zf = 0; zf < 2; zf++) {
            const int zrr = zwm*32 + zf*16 + (zquad & 1)*8 + zrow8;
            const int zcc = (zquad >> 1) * 8;
            zAddrAhi[zf] = smem_addr_u32(&zSmemAhi[0][zrr][zcc]);
            zAddrAlo[zf] = smem_addr_u32(&zSmemAlo[0][zrr][zcc]);
        }
        #pragma unroll
        for (int zg16 = 0; zg16 < 2; zg16++) {
            const int zkr = (zquad & 1)*8 + zrow8;
            const int znc = zwn*32 + zg16*16 + (zquad >> 1)*8;
            zAddrBhi[zg16] = smem_addr_u32(&zSmemBhi[0][zkr][znc]);
            zAddrBlo[zg16] = smem_addr_u32(&zSmemBlo[0][zkr][znc]);
        }
    }
    const u32 zBytesBufA = (u32)(128*24*2);
    const u32 zBytesBufB = (u32)(16*72*2);

    // prefetch tile 0
    uint4 zPfAhi = *reinterpret_cast<const uint4*>(zgAhi);
    uint4 zPfAlo = *reinterpret_cast<const uint4*>(zgAlo);
    uint4 zPfBhi = zDoB ? *reinterpret_cast<const uint4*>(zgBhi) : make_uint4(0,0,0,0);
    uint4 zPfBlo = zDoB ? *reinterpret_cast<const uint4*>(zgBlo) : make_uint4(0,0,0,0);
    *reinterpret_cast<uint4*>(&zSmemAhi[0][zArow][zAseg]) = zPfAhi;
    *reinterpret_cast<uint4*>(&zSmemAlo[0][zArow][zAseg]) = zPfAlo;
    if (zDoB) {
        *reinterpret_cast<uint4*>(&zSmemBhi[0][zBrow][zBcol]) = zPfBhi;
        *reinterpret_cast<uint4*>(&zSmemBlo[0][zBrow][zBcol]) = zPfBlo;
    }
    __syncthreads();

    #pragma unroll 1
    for (int zkt = 0; zkt < 32; zkt++) {
        const int zbuf = zkt & 1;
        if (zkt < 31) {
            zPfAhi = *reinterpret_cast<const uint4*>(zgAhi + (zkt+1)*16);
            zPfAlo = *reinterpret_cast<const uint4*>(zgAlo + (zkt+1)*16);
            if (zDoB) {
                zPfBhi = *reinterpret_cast<const uint4*>(zgBhi + (size_t)(zkt+1)*16*512);
                zPfBlo = *reinterpret_cast<const uint4*>(zgBlo + (size_t)(zkt+1)*16*512);
            }
        }
        u32 zFragAhi[2][4];
        u32 zFragAlo[2][4];
        u32 zFragBhi[2][4];
        u32 zFragBlo[2][4];
        #pragma unroll
        for (int zf = 0; zf < 2; zf++) {
            ld_sm_x4(zFragAhi[zf], zAddrAhi[zf] + zbuf*zBytesBufA);
            ld_sm_x4(zFragAlo[zf], zAddrAlo[zf] + zbuf*zBytesBufA);
        }
        #pragma unroll
        for (int zg16 = 0; zg16 < 2; zg16++) {
            ld_sm_x4_t(zFragBhi[zg16], zAddrBhi[zg16] + zbuf*zBytesBufB);
            ld_sm_x4_t(zFragBlo[zg16], zAddrBlo[zg16] + zbuf*zBytesBufB);
        }
        #pragma unroll
        for (int zf = 0; zf < 2; zf++) {
            #pragma unroll
            for (int zg = 0; zg < 4; zg++) {
                const int zg16  = zg >> 1;
                const int zhsel = (zg & 1) * 2;
                mma16816(zacc[zf][zg], zFragAhi[zf], zFragBhi[zg16][zhsel], zFragBhi[zg16][zhsel+1]);
                mma16816(zacc[zf][zg], zFragAhi[zf], zFragBlo[zg16][zhsel], zFragBlo[zg16][zhsel+1]);
                mma16816(zacc[zf][zg], zFragAlo[zf], zFragBhi[zg16][zhsel], zFragBhi[zg16][zhsel+1]);
            }
        }
        if (zkt < 31) {
            const int znb = zbuf ^ 1;
            *reinterpret_cast<uint4*>(&zSmemAhi[znb][zArow][zAseg]) = zPfAhi;
            *reinterpret_cast<uint4*>(&zSmemAlo[znb][zArow][zAseg]) = zPfAlo;
            if (zDoB) {
                *reinterpret_cast<uint4*>(&zSmemBhi[znb][zBrow][zBcol]) = zPfBhi;
                *reinterpret_cast<uint4*>(&zSmemBlo[znb][zBrow][zBcol]) = zPfBlo;
            }
        }
        __syncthreads();
    }

    // epilogue
    const bool zRelu = (zn0 >= 256);
    #pragma unroll
    for (int zf = 0; zf < 2; zf++) {
        #pragma unroll
        for (int zg = 0; zg < 4; zg++) {
            const int zrow = zm0 + zwm*32 + zf*16 + (zlane >> 2);
            const int zcol = zn0 + zwn*32 + zg*8 + (zlane & 3)*2;
            float2 zv0 = make_float2(zacc[zf][zg][0], zacc[zf][zg][1]);
            float2 zv1 = make_float2(zacc[zf][zg][2], zacc[zf][zg][3]);
            if (zRelu) {
                float2 zbb = *reinterpret_cast<const float2*>(&hb1[zcol - 256]);
                zv0.x = fmaxf(zv0.x + zbb.x, 0.f); zv0.y = fmaxf(zv0.y + zbb.y, 0.f);
                zv1.x = fmaxf(zv1.x + zbb.x, 0.f); zv1.y = fmaxf(zv1.y + zbb.y, 0.f);
            }
            *reinterpret_cast<float2*>(&C[(size_t)zrow * 512 + zcol])       = zv0;
            *reinterpret_cast<float2*>(&C[(size_t)(zrow + 8) * 512 + zcol]) = zv1;
        }
    }
}

// ---------------------------------------------------------------------------
// k2: bx<64 : hs[2048,128] = h1 @ hw2 + hb2      (64x64 tiles, K=256)
//     bx>=64: base[1152,256] = x0@w_x + preq[row/36] + b1  (64x64, K=128)
// ---------------------------------------------------------------------------
__global__ void __launch_bounds__(256) k2(
    const float* __restrict__ C, const float* __restrict__ hw2,
    const float* __restrict__ hb2, const float* __restrict__ x0,
    const float* __restrict__ w1, const float* __restrict__ b1,
    const float* __restrict__ preq,
    float* __restrict__ hs, float* __restrict__ base)
{
    __shared__ float As[2][16][68];
    __shared__ float Bs[2][16][64];
    const int tid = threadIdx.x;
    const int bx  = blockIdx.x;

    const float* A; const float* Bp; int lda, ldb, nt, m0, n0, mode;
    if (bx < 64) {
        mode = 0; const int tm = bx >> 1, tn = bx & 1;
        m0 = tm*64; n0 = tn*64;
        A = C + 256; lda = 512; Bp = hw2; ldb = 128; nt = 256/16;
    } else {
        mode = 1; const int bb = bx - 64; const int tm = bb >> 2, tn = bb & 3;
        m0 = tm*64; n0 = tn*64;
        A = x0; lda = 128; Bp = w1 + (size_t)DS_*H_; ldb = 256; nt = 128/16;
    }

    const int tx = tid & 15, ty = tid >> 4;
    const int ar = tid >> 2;
    const int ac = (tid & 3) << 2;
    const int bkr = tid >> 4;
    const int bn4 = (tid & 15) << 2;

    const float* Ag = A  + (size_t)(m0 + ar) * lda + ac;
    const float* Bg = Bp + (size_t)bkr * ldb + n0 + bn4;

    float2 acc[2][4];
    #pragma unroll
    for (int i = 0; i < 2; i++) {
        #pragma unroll
        for (int j = 0; j < 4; j++) acc[i][j] = make_float2(0.f, 0.f);
    }

    float4 av = *reinterpret_cast<const float4*>(Ag);
    float4 bv = *reinterpret_cast<const float4*>(Bg);
    As[0][ac+0][ar] = av.x; As[0][ac+1][ar] = av.y;
    As[0][ac+2][ar] = av.z; As[0][ac+3][ar] = av.w;
    *reinterpret_cast<float4*>(&Bs[0][bkr][bn4]) = bv;
    __syncthreads();

    #pragma unroll 1
    for (int kt = 0; kt < nt; kt++) {
        const int buf = kt & 1;
        if (kt + 1 < nt) {
            av = *reinterpret_cast<const float4*>(Ag + (kt+1)*16);
            bv = *reinterpret_cast<const float4*>(Bg + (size_t)(kt+1)*16*ldb);
        }
        #pragma unroll
        for (int kk = 0; kk < 16; kk++) {
            float4 a4 = *reinterpret_cast<const float4*>(&As[buf][kk][ty*4]);
            float4 b4 = *reinterpret_cast<const float4*>(&Bs[buf][kk][tx*4]);
            float2 a2v[2] = {{a4.x,a4.y},{a4.z,a4.w}};
            float2 bd[4]  = {{b4.x,b4.x},{b4.y,b4.y},{b4.z,b4.z},{b4.w,b4.w}};
            #pragma unroll
            for (int i = 0; i < 2; i++) {
                #pragma unroll
                for (int j = 0; j < 4; j++)
                    fma2(acc[i][j], a2v[i], bd[j]);
            }
        }
        if (kt + 1 < nt) {
            const int nb = buf ^ 1;
            As[nb][ac+0][ar] = av.x; As[nb][ac+1][ar] = av.y;
            As[nb][ac+2][ar] = av.z; As[nb][ac+3][ar] = av.w;
            *reinterpret_cast<float4*>(&Bs[nb][bkr][bn4]) = bv;
        }
        __syncthreads();
    }

    if (mode == 0) {
        float4 bb = *reinterpret_cast<const float4*>(&hb2[n0 + tx*4]);
        float* Or = hs + (size_t)(m0 + ty*4) * DX_ + n0 + tx*4;
        #pragma unroll
        for (int i = 0; i < 2; i++) {
            float4 lo = make_float4(acc[i][0].x+bb.x, acc[i][1].x+bb.y, acc[i][2].x+bb.z, acc[i][3].x+bb.w);
            float4 hi = make_float4(acc[i][0].y+bb.x, acc[i][1].y+bb.y, acc[i][2].y+bb.z, acc[i][3].y+bb.w);
            *reinterpret_cast<float4*>(Or + (size_t)(2*i  )*DX_) = lo;
            *reinterpret_cast<float4*>(Or + (size_t)(2*i+1)*DX_) = hi;
        }
    } else {
        float4 bb = *reinterpret_cast<const float4*>(&b1[n0 + tx*4]);
        #pragma unroll
        for (int i = 0; i < 2; i++) {
            const int r0 = m0 + ty*4 + 2*i;
            float4 p0 = *reinterpret_cast<const float4*>(&preq[(r0   /Kk_)*H_ + n0 + tx*4]);
            float4 p1 = *reinterpret_cast<const float4*>(&preq[((r0+1)/Kk_)*H_ + n0 + tx*4]);
            float4 lo = make_float4(acc[i][0].x+bb.x+p0.x, acc[i][1].x+bb.y+p0.y,
                                    acc[i][2].x+bb.z+p0.z, acc[i][3].x+bb.w+p0.w);
            float4 hi = make_float4(acc[i][0].y+bb.x+p1.x, acc[i][1].y+bb.y+p1.y,
                                    acc[i][2].y+bb.z+p1.z, acc[i][3].y+bb.w+p1.w);
            *reinterpret_cast<float4*>(&base[(size_t)(r0  )*H_ + n0 + tx*4]) = lo;
            *reinterpret_cast<float4*>(&base[(size_t)(r0+1)*H_ + n0 + tx*4]) = hi;
        }
    }
}

// ---------------------------------------------------------------------------
// att: fused logits + softmax + aggregation + x0 copy. 4 k per block.
// ---------------------------------------------------------------------------
__global__ void __launch_bounds__(256) att_k(
    const float* __restrict__ Cmat, const float* __restrict__ base,
    const float* __restrict__ hsm, const float* __restrict__ w2,
    const float* __restrict__ x0, float* __restrict__ out)
{
    const int b  = blockIdx.x / 9;
    const int kg = blockIdx.x % 9;
    const int bk0 = b * Kk_ + kg * 4;
    const int tid = threadIdx.x;
    const int warp = tid >> 5, lane = tid & 31;

    __shared__ float base_s[4][H_];
    __shared__ float w2s[H_];
    __shared__ float lgt[4][M_];
    __shared__ float ew[4][M_];
    __shared__ float sinv[4];

    for (int idx = tid; idx < 4*H_; idx += 256)
        base_s[idx >> 8][idx & 255] = base[(size_t)(bk0 + (idx >> 8)) * H_ + (idx & 255)];
    w2s[tid] = w2[tid];
    __syncthreads();

    const float* pres = Cmat + (size_t)(b * M_) * 512;
    #pragma unroll
    for (int mi = 0; mi < 8; mi++) {
        const int m = warp * 8 + mi;
        const float* row = pres + (size_t)m * 512;
        float r[8];
        #pragma unroll
        for (int j = 0; j < 8; j++) r[j] = row[lane + 32*j];
        #pragma unroll
        for (int k = 0; k < 4; k++) {
            float acc = 0.f;
            #pragma unroll
            for (int j = 0; j < 8; j++) {
                const int h = lane + 32*j;
                acc = fmaf(fmaxf(r[j] + base_s[k][h], 0.f), w2s[h], acc);
            }
            #pragma unroll
            for (int off = 16; off; off >>= 1)
                acc += __shfl_xor_sync(0xffffffffu, acc, off);
            if (lane == 0) lgt[k][m] = acc;
        }
    }
    __syncthreads();

    if (warp < 4) {
        const int k = warp;
        float l0 = lgt[k][lane], l1 = lgt[k][lane + 32];
        float mx = fmaxf(l0, l1);
        #pragma unroll
        for (int off = 16; off; off >>= 1)
            mx = fmaxf(mx, __shfl_xor_sync(0xffffffffu, mx, off));
        float e0 = expf(l0 - mx), e1 = expf(l1 - mx);
        float s = e0 + e1;
        #pragma unroll
        for (int off = 16; off; off >>= 1)
            s += __shfl_xor_sync(0xffffffffu, s, off);
        ew[k][lane] = e0; ew[k][lane + 32] = e1;
        if (lane == 0) sinv[k] = 1.f / s;
    }
    __syncthreads();

    {
        const int f  = tid & 127;
        const int kp = tid >> 7;
        const int k0 = kp * 2, k1 = k0 + 1;
        const float* hb = hsm + (size_t)(b * M_) * DX_ + f;
        float a0 = 0.f, a1 = 0.f;
        #pragma unroll 8
        for (int m = 0; m < M_; m++) {
            const float v = hb[(size_t)m * DX_];
            a0 = fmaf(ew[k0][m], v, a0);
            a1 = fmaf(ew[k1][m], v, a1);
        }
        out[(size_t)(bk0 + k0) * 256 + 128 + f] = a0 * sinv[k0];
        out[(size_t)(bk0 + k1) * 256 + 128 + f] = a1 * sinv[k1];
    }
    for (int idx = tid; idx < 4 * DX_; idx += 256) {
        const int k = idx >> 7, f = idx & 127;
        out[(size_t)(bk0 + k) * 256 + f] = x0[(size_t)(bk0 + k) * DX_ + f];
    }
}

// ---------------------------------------------------------------------------
extern "C" void kernel_launch(void* const* d_in, const int* in_sizes, int n_in,
                              void* d_out, int out_size)
{
    (void)in_sizes; (void)n_in; (void)out_size;
    const float* s2  = (const float*)d_in[0];
    const float* x0  = (const float*)d_in[1];
    const float* q   = (const float*)d_in[2];
    const float* w1  = (const float*)d_in[3];
    const float* b1  = (const float*)d_in[4];
    const float* w2  = (const float*)d_in[5];
    const float* hw1 = (const float*)d_in[7];
    const float* hb1 = (const float*)d_in[8];
    const float* hw2 = (const float*)d_in[9];
    const float* hb2 = (const float*)d_in[10];
    float* out = (float*)d_out;

    float *preq, *C, *hs, *base;
    __nv_bfloat16 *Ahi, *Alo, *Whi, *Wlo;
    cudaGetSymbolAddress((void**)&preq, g_preq);
    cudaGetSymbolAddress((void**)&C,    g_C);
    cudaGetSymbolAddress((void**)&hs,   g_hs);
    cudaGetSymbolAddress((void**)&base, g_base);
    cudaGetSymbolAddress((void**)&Ahi,  g_Ahi);
    cudaGetSymbolAddress((void**)&Alo,  g_Alo);
    cudaGetSymbolAddress((void**)&Whi,  g_Whi);
    cudaGetSymbolAddress((void**)&Wlo,  g_Wlo);

    // P: bf16 hi/lo split of s2 and [w_s|hw1], + preq
    prep_k<<<672, 256>>>(s2, w1, hw1, q, Ahi, Alo, Whi, Wlo, preq);
    // L1: tensor-core bf16x3 GEMM -> C (relu+hb1 fused for cols>=256)
    k1_mma<<<128, 256>>>(Ahi, Alo, Whi, Wlo, hb1, C);
    // L2: hs + base
    k2<<<136, 256>>>(C, hw2, hb2, x0, w1, b1, preq, hs, base);
    // L3: fused attention + output
    att_k<<<288, 256>>>(C, base, hs, w2, x0, out);
}

// round 11
// speedup vs baseline: 1.2005x; 1.0355x over previous
#include <cuda_runtime.h>
#include <cuda_bf16.h>
#include <cstdint>
#include <math.h>

typedef unsigned int u32;

#define B_  32
#define M_  64
#define Kk_ 36
#define DS_ 512
#define DX_ 128
#define DQ_ 512
#define H_  256
#define ROWS_S 2048
#define ROWS_X 1152

// Scratch (allocation-free rule: __device__ globals)
__device__ __align__(16) float g_preq[B_*H_];
__device__ __align__(16) float g_C[ROWS_S*512];      // 0:256 pre_s (raw), 256:512 h1=relu(..+hb1)
__device__ __align__(16) float g_hs[ROWS_S*DX_];
__device__ __align__(16) float g_base[ROWS_X*H_];
__device__ __align__(16) __nv_bfloat16 g_Ahi[ROWS_S*512];
__device__ __align__(16) __nv_bfloat16 g_Alo[ROWS_S*512];
__device__ __align__(16) __nv_bfloat16 g_Whi[512*512];  // cols 0:256 w_s, 256:512 hw1
__device__ __align__(16) __nv_bfloat16 g_Wlo[512*512];

__device__ __forceinline__ void fma2(float2 &d, const float2 &a, const float2 &b) {
    asm("fma.rn.f32x2 %0, %1, %2, %0;"
        : "+l"(reinterpret_cast<unsigned long long&>(d))
        : "l"(reinterpret_cast<const unsigned long long&>(a)),
          "l"(reinterpret_cast<const unsigned long long&>(b)));
}

__device__ __forceinline__ u32 smem_addr_u32(const void* zp) {
    return (u32)__cvta_generic_to_shared(zp);
}
__device__ __forceinline__ void ld_sm_x4(u32* zr, u32 zaddr) {
    asm volatile("ldmatrix.sync.aligned.m8n8.x4.shared.b16 {%0,%1,%2,%3}, [%4];"
        : "=r"(zr[0]), "=r"(zr[1]), "=r"(zr[2]), "=r"(zr[3]) : "r"(zaddr));
}
__device__ __forceinline__ void ld_sm_x4_t(u32* zr, u32 zaddr) {
    asm volatile("ldmatrix.sync.aligned.m8n8.x4.trans.shared.b16 {%0,%1,%2,%3}, [%4];"
        : "=r"(zr[0]), "=r"(zr[1]), "=r"(zr[2]), "=r"(zr[3]) : "r"(zaddr));
}
__device__ __forceinline__ void mma16816(float* zc, const u32* za, u32 zb0, u32 zb1) {
    asm volatile("mma.sync.aligned.m16n8k16.row.col.f32.bf16.bf16.f32 "
        "{%0,%1,%2,%3},{%4,%5,%6,%7},{%8,%9},{%0,%1,%2,%3};"
        : "+f"(zc[0]), "+f"(zc[1]), "+f"(zc[2]), "+f"(zc[3])
        : "r"(za[0]), "r"(za[1]), "r"(za[2]), "r"(za[3]), "r"(zb0), "r"(zb1));
}

// ---------------------------------------------------------------------------
// prep: bx<512  : convert s2 -> (Ahi, Alo)
//       512..639: convert [w_s|hw1] -> (Whi,Wlo)
//       bx>=640 : preq[b] = q[b] @ w_q
// ---------------------------------------------------------------------------
__global__ void __launch_bounds__(256) prep_k(
    const float* __restrict__ s2, const float* __restrict__ w1,
    const float* __restrict__ hw1, const float* __restrict__ q,
    __nv_bfloat16* __restrict__ Ahi, __nv_bfloat16* __restrict__ Alo,
    __nv_bfloat16* __restrict__ Whi, __nv_bfloat16* __restrict__ Wlo,
    float* __restrict__ preq)
{
    const int ztid = threadIdx.x;
    const int zbx  = blockIdx.x;

    if (zbx < 512) {
        size_t zoff = ((size_t)zbx * 256 + ztid) * 8;
        float4 zva = *reinterpret_cast<const float4*>(s2 + zoff);
        float4 zvb = *reinterpret_cast<const float4*>(s2 + zoff + 4);
        float zv[8] = {zva.x,zva.y,zva.z,zva.w,zvb.x,zvb.y,zvb.z,zvb.w};
        __nv_bfloat16 zhi[8];
        __nv_bfloat16 zlo[8];
        #pragma unroll
        for (int zi = 0; zi < 8; zi++) {
            zhi[zi] = __float2bfloat16(zv[zi]);
            zlo[zi] = __float2bfloat16(zv[zi] - __bfloat162float(zhi[zi]));
        }
        *reinterpret_cast<uint4*>(Ahi + zoff) = *reinterpret_cast<uint4*>(zhi);
        *reinterpret_cast<uint4*>(Alo + zoff) = *reinterpret_cast<uint4*>(zlo);
        return;
    }
    if (zbx < 640) {
        size_t zoff = ((size_t)(zbx - 512) * 256 + ztid) * 8;
        const int zk = (int)(zoff >> 9);
        const int zn = (int)(zoff & 511);
        const float* zsrc = (zn < 256) ? (w1 + (size_t)zk*256 + zn)
                                       : (hw1 + (size_t)zk*256 + (zn - 256));
        float4 zva = *reinterpret_cast<const float4*>(zsrc);
        float4 zvb = *reinterpret_cast<const float4*>(zsrc + 4);
        float zv[8] = {zva.x,zva.y,zva.z,zva.w,zvb.x,zvb.y,zvb.z,zvb.w};
        __nv_bfloat16 zhi[8];
        __nv_bfloat16 zlo[8];
        #pragma unroll
        for (int zi = 0; zi < 8; zi++) {
            zhi[zi] = __float2bfloat16(zv[zi]);
            zlo[zi] = __float2bfloat16(zv[zi] - __bfloat162float(zhi[zi]));
        }
        *reinterpret_cast<uint4*>(Whi + zoff) = *reinterpret_cast<uint4*>(zhi);
        *reinterpret_cast<uint4*>(Wlo + zoff) = *reinterpret_cast<uint4*>(zlo);
        return;
    }
    __shared__ float zqs[DQ_];
    const int zb = zbx - 640;
    for (int zd = ztid; zd < DQ_; zd += 256) zqs[zd] = q[zb*DQ_ + zd];
    __syncthreads();
    const float* zwq = w1 + (size_t)(DS_ + DX_) * H_ + ztid;
    float zacc0 = 0.f;
    float zacc1 = 0.f;
    #pragma unroll 8
    for (int zd = 0; zd < DQ_; zd += 2) {
        zacc0 = fmaf(zqs[zd],   zwq[(size_t)zd*H_],     zacc0);
        zacc1 = fmaf(zqs[zd+1], zwq[(size_t)(zd+1)*H_], zacc1);
    }
    preq[zb*H_ + ztid] = zacc0 + zacc1;
}

// ---------------------------------------------------------------------------
// k1_mma: C[2048,512] = [ s2@w_s | relu(s2@hw1+hb1) ] via bf16x3 tensor MMA.
//   128x64 block tile, BK=16, 256 thr (8 warps: 4m x 2n, warp tile 32x32).
//   grid = 128 blocks. Double-buffered smem, padded strides.
// ---------------------------------------------------------------------------
__global__ void __launch_bounds__(256) k1_mma(
    const __nv_bfloat16* __restrict__ Ahi, const __nv_bfloat16* __restrict__ Alo,
    const __nv_bfloat16* __restrict__ Whi, const __nv_bfloat16* __restrict__ Wlo,
    const float* __restrict__ hb1, float* __restrict__ C)
{
    __shared__ __align__(16) __nv_bfloat16 zSmemAhi[2][128][24];
    __shared__ __align__(16) __nv_bfloat16 zSmemAlo[2][128][24];
    __shared__ __align__(16) __nv_bfloat16 zSmemBhi[2][16][72];
    __shared__ __align__(16) __nv_bfloat16 zSmemBlo[2][16][72];

    const int ztid  = threadIdx.x;
    const int zbx   = blockIdx.x;
    const int zbm   = zbx >> 3;
    const int zbn   = zbx & 7;
    const int zm0   = zbm * 128;
    const int zn0   = zbn * 64;
    const int zwarp = ztid >> 5;
    const int zlane = ztid & 31;
    const int zwm   = zwarp & 3;
    const int zwn   = zwarp >> 2;

    const int zArow = ztid >> 1;
    const int zAseg = (ztid & 1) * 8;
    const __nv_bfloat16* zgAhi = Ahi + (size_t)(zm0 + zArow) * 512 + zAseg;
    const __nv_bfloat16* zgAlo = Alo + (size_t)(zm0 + zArow) * 512 + zAseg;
    const int zBrow = ztid >> 3;
    const int zBcol = (ztid & 7) * 8;
    const __nv_bfloat16* zgBhi = Whi + (size_t)zBrow * 512 + zn0 + zBcol;
    const __nv_bfloat16* zgBlo = Wlo + (size_t)zBrow * 512 + zn0 + zBcol;
    const bool zDoB = (ztid < 128);

    float zacc[2][4][4];
    #pragma unroll
    for (int zf = 0; zf < 2; zf++) {
        #pragma unroll
        for (int zg = 0; zg < 4; zg++) {
            #pragma unroll
            for (int ze = 0; ze < 4; ze++) zacc[zf][zg][ze] = 0.f;
        }
    }

    u32 zAddrAhi[2];
    u32 zAddrAlo[2];
    u32 zAddrBhi[2];
    u32 zAddrBlo[2];
    {
        const int zquad = zlane >> 3;
        const int zrow8 = zlane & 7;
        #pragma unroll
        for (int zf = 0; zf < 2; zf++) {
            const int zrr = zwm*32 + zf*16 + (zquad & 1)*8 + zrow8;
            const int zcc = (zquad >> 1) * 8;
            zAddrAhi[zf] = smem_addr_u32(&zSmemAhi[0][zrr][zcc]);
            zAddrAlo[zf] = smem_addr_u32(&zSmemAlo[0][zrr][zcc]);
        }
        #pragma unroll
        for (int zg16 = 0; zg16 < 2; zg16++) {
            const int zkr = (zquad & 1)*8 + zrow8;
            const int znc = zwn*32 + zg16*16 + (zquad >> 1)*8;
            zAddrBhi[zg16] = smem_addr_u32(&zSmemBhi[0][zkr][znc]);
            zAddrBlo[zg16] = smem_addr_u32(&zSmemBlo[0][zkr][znc]);
        }
    }
    const u32 zBytesBufA = (u32)(128*24*2);
    const u32 zBytesBufB = (u32)(16*72*2);

    uint4 zPfAhi = *reinterpret_cast<const uint4*>(zgAhi);
    uint4 zPfAlo = *reinterpret_cast<const uint4*>(zgAlo);
    uint4 zPfBhi = zDoB ? *reinterpret_cast<const uint4*>(zgBhi) : make_uint4(0,0,0,0);
    uint4 zPfBlo = zDoB ? *reinterpret_cast<const uint4*>(zgBlo) : make_uint4(0,0,0,0);
    *reinterpret_cast<uint4*>(&zSmemAhi[0][zArow][zAseg]) = zPfAhi;
    *reinterpret_cast<uint4*>(&zSmemAlo[0][zArow][zAseg]) = zPfAlo;
    if (zDoB) {
        *reinterpret_cast<uint4*>(&zSmemBhi[0][zBrow][zBcol]) = zPfBhi;
        *reinterpret_cast<uint4*>(&zSmemBlo[0][zBrow][zBcol]) = zPfBlo;
    }
    __syncthreads();

    #pragma unroll 1
    for (int zkt = 0; zkt < 32; zkt++) {
        const int zbuf = zkt & 1;
        if (zkt < 31) {
            zPfAhi = *reinterpret_cast<const uint4*>(zgAhi + (zkt+1)*16);
            zPfAlo = *reinterpret_cast<const uint4*>(zgAlo + (zkt+1)*16);
            if (zDoB) {
                zPfBhi = *reinterpret_cast<const uint4*>(zgBhi + (size_t)(zkt+1)*16*512);
                zPfBlo = *reinterpret_cast<const uint4*>(zgBlo + (size_t)(zkt+1)*16*512);
            }
        }
        u32 zFragAhi[2][4];
        u32 zFragAlo[2][4];
        u32 zFragBhi[2][4];
        u32 zFragBlo[2][4];
        #pragma unroll
        for (int zf = 0; zf < 2; zf++) {
            ld_sm_x4(zFragAhi[zf], zAddrAhi[zf] + zbuf*zBytesBufA);
            ld_sm_x4(zFragAlo[zf], zAddrAlo[zf] + zbuf*zBytesBufA);
        }
        #pragma unroll
        for (int zg16 = 0; zg16 < 2; zg16++) {
            ld_sm_x4_t(zFragBhi[zg16], zAddrBhi[zg16] + zbuf*zBytesBufB);
            ld_sm_x4_t(zFragBlo[zg16], zAddrBlo[zg16] + zbuf*zBytesBufB);
        }
        #pragma unroll
        for (int zf = 0; zf < 2; zf++) {
            #pragma unroll
            for (int zg = 0; zg < 4; zg++) {
                const int zg16  = zg >> 1;
                const int zhsel = (zg & 1) * 2;
                mma16816(zacc[zf][zg], zFragAhi[zf], zFragBhi[zg16][zhsel], zFragBhi[zg16][zhsel+1]);
                mma16816(zacc[zf][zg], zFragAhi[zf], zFragBlo[zg16][zhsel], zFragBlo[zg16][zhsel+1]);
                mma16816(zacc[zf][zg], zFragAlo[zf], zFragBhi[zg16][zhsel], zFragBhi[zg16][zhsel+1]);
            }
        }
        if (zkt < 31) {
            const int znb = zbuf ^ 1;
            *reinterpret_cast<uint4*>(&zSmemAhi[znb][zArow][zAseg]) = zPfAhi;
            *reinterpret_cast<uint4*>(&zSmemAlo[znb][zArow][zAseg]) = zPfAlo;
            if (zDoB) {
                *reinterpret_cast<uint4*>(&zSmemBhi[znb][zBrow][zBcol]) = zPfBhi;
                *reinterpret_cast<uint4*>(&zSmemBlo[znb][zBrow][zBcol]) = zPfBlo;
            }
        }
        __syncthreads();
    }

    const bool zRelu = (zn0 >= 256);
    #pragma unroll
    for (int zf = 0; zf < 2; zf++) {
        #pragma unroll
        for (int zg = 0; zg < 4; zg++) {
            const int zrow = zm0 + zwm*32 + zf*16 + (zlane >> 2);
            const int zcol = zn0 + zwn*32 + zg*8 + (zlane & 3)*2;
            float2 zv0 = make_float2(zacc[zf][zg][0], zacc[zf][zg][1]);
            float2 zv1 = make_float2(zacc[zf][zg][2], zacc[zf][zg][3]);
            if (zRelu) {
                float2 zbb = *reinterpret_cast<const float2*>(&hb1[zcol - 256]);
                zv0.x = fmaxf(zv0.x + zbb.x, 0.f); zv0.y = fmaxf(zv0.y + zbb.y, 0.f);
                zv1.x = fmaxf(zv1.x + zbb.x, 0.f); zv1.y = fmaxf(zv1.y + zbb.y, 0.f);
            }
            *reinterpret_cast<float2*>(&C[(size_t)zrow * 512 + zcol])       = zv0;
            *reinterpret_cast<float2*>(&C[(size_t)(zrow + 8) * 512 + zcol]) = zv1;
        }
    }
}

// ---------------------------------------------------------------------------
// k2: bx<64 : hs[2048,128] = h1 @ hw2 + hb2      (64x64 tiles, K=256)
//     bx>=64: base[1152,256] = x0@w_x + preq[row/36] + b1  (64x64, K=128)
// ---------------------------------------------------------------------------
__global__ void __launch_bounds__(256) k2(
    const float* __restrict__ C, const float* __restrict__ hw2,
    const float* __restrict__ hb2, const float* __restrict__ x0,
    const float* __restrict__ w1, const float* __restrict__ b1,
    const float* __restrict__ preq,
    float* __restrict__ hs, float* __restrict__ base)
{
    __shared__ float As[2][16][68];
    __shared__ float Bs[2][16][64];
    const int tid = threadIdx.x;
    const int bx  = blockIdx.x;

    const float* A; const float* Bp; int lda, ldb, nt, m0, n0, mode;
    if (bx < 64) {
        mode = 0; const int tm = bx >> 1, tn = bx & 1;
        m0 = tm*64; n0 = tn*64;
        A = C + 256; lda = 512; Bp = hw2; ldb = 128; nt = 256/16;
    } else {
        mode = 1; const int bb = bx - 64; const int tm = bb >> 2, tn = bb & 3;
        m0 = tm*64; n0 = tn*64;
        A = x0; lda = 128; Bp = w1 + (size_t)DS_*H_; ldb = 256; nt = 128/16;
    }

    const int tx = tid & 15, ty = tid >> 4;
    const int ar = tid >> 2;
    const int ac = (tid & 3) << 2;
    const int bkr = tid >> 4;
    const int bn4 = (tid & 15) << 2;

    const float* Ag = A  + (size_t)(m0 + ar) * lda + ac;
    const float* Bg = Bp + (size_t)bkr * ldb + n0 + bn4;

    float2 acc[2][4];
    #pragma unroll
    for (int i = 0; i < 2; i++) {
        #pragma unroll
        for (int j = 0; j < 4; j++) acc[i][j] = make_float2(0.f, 0.f);
    }

    float4 av = *reinterpret_cast<const float4*>(Ag);
    float4 bv = *reinterpret_cast<const float4*>(Bg);
    As[0][ac+0][ar] = av.x; As[0][ac+1][ar] = av.y;
    As[0][ac+2][ar] = av.z; As[0][ac+3][ar] = av.w;
    *reinterpret_cast<float4*>(&Bs[0][bkr][bn4]) = bv;
    __syncthreads();

    #pragma unroll 1
    for (int kt = 0; kt < nt; kt++) {
        const int buf = kt & 1;
        if (kt + 1 < nt) {
            av = *reinterpret_cast<const float4*>(Ag + (kt+1)*16);
            bv = *reinterpret_cast<const float4*>(Bg + (size_t)(kt+1)*16*ldb);
        }
        #pragma unroll
        for (int kk = 0; kk < 16; kk++) {
            float4 a4 = *reinterpret_cast<const float4*>(&As[buf][kk][ty*4]);
            float4 b4 = *reinterpret_cast<const float4*>(&Bs[buf][kk][tx*4]);
            float2 a2v[2] = {{a4.x,a4.y},{a4.z,a4.w}};
            float2 bd[4]  = {{b4.x,b4.x},{b4.y,b4.y},{b4.z,b4.z},{b4.w,b4.w}};
            #pragma unroll
            for (int i = 0; i < 2; i++) {
                #pragma unroll
                for (int j = 0; j < 4; j++)
                    fma2(acc[i][j], a2v[i], bd[j]);
            }
        }
        if (kt + 1 < nt) {
            const int nb = buf ^ 1;
            As[nb][ac+0][ar] = av.x; As[nb][ac+1][ar] = av.y;
            As[nb][ac+2][ar] = av.z; As[nb][ac+3][ar] = av.w;
            *reinterpret_cast<float4*>(&Bs[nb][bkr][bn4]) = bv;
        }
        __syncthreads();
    }

    if (mode == 0) {
        float4 bb = *reinterpret_cast<const float4*>(&hb2[n0 + tx*4]);
        float* Or = hs + (size_t)(m0 + ty*4) * DX_ + n0 + tx*4;
        #pragma unroll
        for (int i = 0; i < 2; i++) {
            float4 lo = make_float4(acc[i][0].x+bb.x, acc[i][1].x+bb.y, acc[i][2].x+bb.z, acc[i][3].x+bb.w);
            float4 hi = make_float4(acc[i][0].y+bb.x, acc[i][1].y+bb.y, acc[i][2].y+bb.z, acc[i][3].y+bb.w);
            *reinterpret_cast<float4*>(Or + (size_t)(2*i  )*DX_) = lo;
            *reinterpret_cast<float4*>(Or + (size_t)(2*i+1)*DX_) = hi;
        }
    } else {
        float4 bb = *reinterpret_cast<const float4*>(&b1[n0 + tx*4]);
        #pragma unroll
        for (int i = 0; i < 2; i++) {
            const int r0 = m0 + ty*4 + 2*i;
            float4 p0 = *reinterpret_cast<const float4*>(&preq[(r0   /Kk_)*H_ + n0 + tx*4]);
            float4 p1 = *reinterpret_cast<const float4*>(&preq[((r0+1)/Kk_)*H_ + n0 + tx*4]);
            float4 lo = make_float4(acc[i][0].x+bb.x+p0.x, acc[i][1].x+bb.y+p0.y,
                                    acc[i][2].x+bb.z+p0.z, acc[i][3].x+bb.w+p0.w);
            float4 hi = make_float4(acc[i][0].y+bb.x+p1.x, acc[i][1].y+bb.y+p1.y,
                                    acc[i][2].y+bb.z+p1.z, acc[i][3].y+bb.w+p1.w);
            *reinterpret_cast<float4*>(&base[(size_t)(r0  )*H_ + n0 + tx*4]) = lo;
            *reinterpret_cast<float4*>(&base[(size_t)(r0+1)*H_ + n0 + tx*4]) = hi;
        }
    }
}

// ---------------------------------------------------------------------------
// att: fused logits + softmax + aggregation + x0 copy. 4 k per block.
//      Logits use 4 interleaved butterflies (pipelined SHFL chains).
// ---------------------------------------------------------------------------
__global__ void __launch_bounds__(256) att_k(
    const float* __restrict__ Cmat, const float* __restrict__ base,
    const float* __restrict__ hsm, const float* __restrict__ w2,
    const float* __restrict__ x0, float* __restrict__ out)
{
    const int b  = blockIdx.x / 9;
    const int kg = blockIdx.x % 9;
    const int bk0 = b * Kk_ + kg * 4;
    const int tid = threadIdx.x;
    const int warp = tid >> 5, lane = tid & 31;

    __shared__ float base_s[4][H_];
    __shared__ float w2s[H_];
    __shared__ float lgt[4][M_];
    __shared__ float ew[4][M_];
    __shared__ float sinv[4];

    for (int idx = tid; idx < 4*H_; idx += 256)
        base_s[idx >> 8][idx & 255] = base[(size_t)(bk0 + (idx >> 8)) * H_ + (idx & 255)];
    w2s[tid] = w2[tid];
    __syncthreads();

    const float* pres = Cmat + (size_t)(b * M_) * 512;
    #pragma unroll
    for (int mi = 0; mi < 8; mi++) {
        const int m = warp * 8 + mi;
        const float* row = pres + (size_t)m * 512;
        float r[8];
        #pragma unroll
        for (int j = 0; j < 8; j++) r[j] = row[lane + 32*j];
        float a0 = 0.f, a1 = 0.f, a2 = 0.f, a3 = 0.f;
        #pragma unroll
        for (int j = 0; j < 8; j++) {
            const int h = lane + 32*j;
            const float rv = r[j];
            const float wv = w2s[h];
            a0 = fmaf(fmaxf(rv + base_s[0][h], 0.f), wv, a0);
            a1 = fmaf(fmaxf(rv + base_s[1][h], 0.f), wv, a1);
            a2 = fmaf(fmaxf(rv + base_s[2][h], 0.f), wv, a2);
            a3 = fmaf(fmaxf(rv + base_s[3][h], 0.f), wv, a3);
        }
        // interleaved butterflies: 4 independent SHFL chains pipeline
        #pragma unroll
        for (int off = 16; off; off >>= 1) {
            a0 += __shfl_xor_sync(0xffffffffu, a0, off);
            a1 += __shfl_xor_sync(0xffffffffu, a1, off);
            a2 += __shfl_xor_sync(0xffffffffu, a2, off);
            a3 += __shfl_xor_sync(0xffffffffu, a3, off);
        }
        if (lane == 0) {
            lgt[0][m] = a0; lgt[1][m] = a1; lgt[2][m] = a2; lgt[3][m] = a3;
        }
    }
    __syncthreads();

    if (warp < 4) {
        const int k = warp;
        float l0 = lgt[k][lane], l1 = lgt[k][lane + 32];
        float mx = fmaxf(l0, l1);
        #pragma unroll
        for (int off = 16; off; off >>= 1)
            mx = fmaxf(mx, __shfl_xor_sync(0xffffffffu, mx, off));
        float e0 = expf(l0 - mx), e1 = expf(l1 - mx);
        float s = e0 + e1;
        #pragma unroll
        for (int off = 16; off; off >>= 1)
            s += __shfl_xor_sync(0xffffffffu, s, off);
        ew[k][lane] = e0; ew[k][lane + 32] = e1;
        if (lane == 0) sinv[k] = 1.f / s;
    }
    __syncthreads();

    {
        const int f  = tid & 127;
        const int kp = tid >> 7;
        const int k0 = kp * 2, k1 = k0 + 1;
        const float* hb = hsm + (size_t)(b * M_) * DX_ + f;
        float a0 = 0.f, a1 = 0.f;
        #pragma unroll 8
        for (int m = 0; m < M_; m++) {
            const float v = hb[(size_t)m * DX_];
            a0 = fmaf(ew[k0][m], v, a0);
            a1 = fmaf(ew[k1][m], v, a1);
        }
        out[(size_t)(bk0 + k0) * 256 + 128 + f] = a0 * sinv[k0];
        out[(size_t)(bk0 + k1) * 256 + 128 + f] = a1 * sinv[k1];
    }
    for (int idx = tid; idx < 4 * DX_; idx += 256) {
        const int k = idx >> 7, f = idx & 127;
        out[(size_t)(bk0 + k) * 256 + f] = x0[(size_t)(bk0 + k) * DX_ + f];
    }
}

// ---------------------------------------------------------------------------
extern "C" void kernel_launch(void* const* d_in, const int* in_sizes, int n_in,
                              void* d_out, int out_size)
{
    (void)in_sizes; (void)n_in; (void)out_size;
    const float* s2  = (const float*)d_in[0];
    const float* x0  = (const float*)d_in[1];
    const float* q   = (const float*)d_in[2];
    const float* w1  = (const float*)d_in[3];
    const float* b1  = (const float*)d_in[4];
    const float* w2  = (const float*)d_in[5];
    const float* hw1 = (const float*)d_in[7];
    const float* hb1 = (const float*)d_in[8];
    const float* hw2 = (const float*)d_in[9];
    const float* hb2 = (const float*)d_in[10];
    float* out = (float*)d_out;

    float *preq, *C, *hs, *base;
    __nv_bfloat16 *Ahi, *Alo, *Whi, *Wlo;
    cudaGetSymbolAddress((void**)&preq, g_preq);
    cudaGetSymbolAddress((void**)&C,    g_C);
    cudaGetSymbolAddress((void**)&hs,   g_hs);
    cudaGetSymbolAddress((void**)&base, g_base);
    cudaGetSymbolAddress((void**)&Ahi,  g_Ahi);
    cudaGetSymbolAddress((void**)&Alo,  g_Alo);
    cudaGetSymbolAddress((void**)&Whi,  g_Whi);
    cudaGetSymbolAddress((void**)&Wlo,  g_Wlo);

    // P: bf16 hi/lo split of s2 and [w_s|hw1], + preq
    prep_k<<<672, 256>>>(s2, w1, hw1, q, Ahi, Alo, Whi, Wlo, preq);
    // L1: tensor-core bf16x3 GEMM -> C (relu+hb1 fused for cols>=256)
    k1_mma<<<128, 256>>>(Ahi, Alo, Whi, Wlo, hb1, C);
    // L2: hs + base
    k2<<<136, 256>>>(C, hw2, hb2, x0, w1, b1, preq, hs, base);
    // L3: fused attention + output
    att_k<<<288, 256>>>(C, base, hs, w2, x0, out);
}